// round 10
// baseline (speedup 1.0000x reference)
#include <cuda_runtime.h>
#include <cuda_bf16.h>
#include <cstdint>

// Problem constants (fixed by the dataset).
#define BSZ     16
#define DIM     4096
#define NH      32
#define NKV     8
#define HD      128
#define MSL     4096
#define NSPLIT  16
#define SCHUNK  256          // MSL / NSPLIT
#define KVROW   (NKV * HD)   // 1024 floats per cache position
#define SCALE   0.08838834764831845f   // 1/sqrt(128)
#define NROWS   6144         // 4096 q + 1024 k + 1024 v

// ---------------------------------------------------------------------------
// Scratch
// ---------------------------------------------------------------------------
__device__ __align__(16) float g_q[BSZ * NH * HD];
__device__ __align__(16) float g_k[BSZ * NKV * HD];
__device__ __align__(16) float g_v[BSZ * NKV * HD];
__device__ __align__(16) float g_p [2 * NROWS * BSZ];
__device__ __align__(16) float g_po[2 * DIM   * BSZ];
__device__ __align__(16) float g_op[BSZ * NKV * NSPLIT * 4 * HD];
__device__ float g_m[BSZ * NKV * NSPLIT * 4];
__device__ float g_l[BSZ * NKV * NSPLIT * 4];
__device__ __align__(16) float g_attn[BSZ * DIM];

__device__ __forceinline__ int load_sp(const int* p) {
    int v = *p;
    if (v < 0 || v >= 1000000) v = (int)__int_as_float(v);
    return v;
}

typedef unsigned long long ull;

__device__ __forceinline__ ull ffma2(ull a, ull b, ull c) {
    ull d;
    asm("fma.rn.f32x2 %0, %1, %2, %3;" : "=l"(d) : "l"(a), "l"(b), "l"(c));
    return d;
}
__device__ __forceinline__ ull fmul2(ull a, ull b) {
    ull d;
    asm("mul.rn.f32x2 %0, %1, %2;" : "=l"(d) : "l"(a), "l"(b));
    return d;
}
__device__ __forceinline__ ull fpack2(float lo, float hi) {
    ull d;
    asm("mov.b64 %0, {%1, %2};" : "=l"(d) : "f"(lo), "f"(hi));
    return d;
}
__device__ __forceinline__ float ull_lo(ull v) {
    return __uint_as_float((unsigned)(v & 0xffffffffull));
}
__device__ __forceinline__ float ull_hi(ull v) {
    return __uint_as_float((unsigned)(v >> 32));
}
// horizontal: lo + hi
__device__ __forceinline__ float hsum2(ull v) { return ull_lo(v) + ull_hi(v); }

// 9-shuffle joint reduce of 4 per-lane partials; every lane ends with the
// full sum of value (lane & 3).
__device__ __forceinline__ float red4x(float d0, float d1, float d2, float d3, int lane)
{
    d0 += __shfl_xor_sync(0xffffffffu, d0, 1);
    d1 += __shfl_xor_sync(0xffffffffu, d1, 1);
    d2 += __shfl_xor_sync(0xffffffffu, d2, 1);
    d3 += __shfl_xor_sync(0xffffffffu, d3, 1);
    float aa = (lane & 1) ? d1 : d0;
    float bb = (lane & 1) ? d3 : d2;
    aa += __shfl_xor_sync(0xffffffffu, aa, 2);
    bb += __shfl_xor_sync(0xffffffffu, bb, 2);
    float cc = (lane & 2) ? bb : aa;
    cc += __shfl_xor_sync(0xffffffffu, cc, 4);
    cc += __shfl_xor_sync(0xffffffffu, cc, 8);
    cc += __shfl_xor_sync(0xffffffffu, cc, 16);
    return cc;
}

// Packed 4-head dot (k row fragment vs 4 q fragments) + reduce.
__device__ __forceinline__ float dot4p(const ulonglong2 k2, const ull qp[4][2], int lane)
{
    ull t0 = ffma2(k2.y, qp[0][1], fmul2(k2.x, qp[0][0]));
    ull t1 = ffma2(k2.y, qp[1][1], fmul2(k2.x, qp[1][0]));
    ull t2 = ffma2(k2.y, qp[2][1], fmul2(k2.x, qp[2][0]));
    ull t3 = ffma2(k2.y, qp[3][1], fmul2(k2.x, qp[3][0]));
    return red4x(hsum2(t0), hsum2(t1), hsum2(t2), hsum2(t3), lane);
}

// ---------------------------------------------------------------------------
// Kernel 1: QKV GEMV.  Block = 16 rows, shared (batch-half, col-split).
// Warp = 2 rows x 8 batches x 2048 cols, c-loop unrolled x2.
// ---------------------------------------------------------------------------
__global__ void __launch_bounds__(256, 3) k_gemv_qkv(
    const float* __restrict__ x,
    const float* __restrict__ wq,
    const float* __restrict__ wk,
    const float* __restrict__ wv)
{
    const int warp = threadIdx.x >> 5;
    const int lane = threadIdx.x & 31;
    const int cs   = blockIdx.x & 1;
    const int bh   = (blockIdx.x >> 1) & 1;
    const int rb   = blockIdx.x >> 2;
    const int r0   = rb * 16 + warp * 2;
    const int b0   = bh * 8;
    const int c0   = cs * 2048;

    const float* W; int rbase;
    if (r0 < 4096)      { W = wq; rbase = r0;        }
    else if (r0 < 5120) { W = wk; rbase = r0 - 4096; }
    else                { W = wv; rbase = r0 - 5120; }

    const float* w0p = W + (size_t)(rbase + 0) * DIM + c0;
    const float* w1p = W + (size_t)(rbase + 1) * DIM + c0;
    const float* xp  = x + (size_t)b0 * DIM + c0;

    ull acc[2][8];
#pragma unroll
    for (int r = 0; r < 2; r++)
#pragma unroll
        for (int b = 0; b < 8; b++) acc[r][b] = 0ull;

    const int off = lane * 4;
    for (int c = 0; c < 2048; c += 256) {
        const ulonglong2 w0a = *reinterpret_cast<const ulonglong2*>(w0p + c + off);
        const ulonglong2 w1a = *reinterpret_cast<const ulonglong2*>(w1p + c + off);
        const ulonglong2 w0b = *reinterpret_cast<const ulonglong2*>(w0p + c + 128 + off);
        const ulonglong2 w1b = *reinterpret_cast<const ulonglong2*>(w1p + c + 128 + off);
#pragma unroll
        for (int b = 0; b < 8; b++) {
            const ulonglong2 xa =
                *reinterpret_cast<const ulonglong2*>(xp + (size_t)b * DIM + c + off);
            const ulonglong2 xb =
                *reinterpret_cast<const ulonglong2*>(xp + (size_t)b * DIM + c + 128 + off);
            acc[0][b] = ffma2(w0a.x, xa.x, acc[0][b]);
            acc[0][b] = ffma2(w0a.y, xa.y, acc[0][b]);
            acc[1][b] = ffma2(w1a.x, xa.x, acc[1][b]);
            acc[1][b] = ffma2(w1a.y, xa.y, acc[1][b]);
            acc[0][b] = ffma2(w0b.x, xb.x, acc[0][b]);
            acc[0][b] = ffma2(w0b.y, xb.y, acc[0][b]);
            acc[1][b] = ffma2(w1b.x, xb.x, acc[1][b]);
            acc[1][b] = ffma2(w1b.y, xb.y, acc[1][b]);
        }
    }

#pragma unroll
    for (int r = 0; r < 2; r++) {
        float res = 0.f;
#pragma unroll
        for (int b = 0; b < 8; b++) {
            float v = hsum2(acc[r][b]);
            v += __shfl_xor_sync(0xffffffffu, v, 16);
            v += __shfl_xor_sync(0xffffffffu, v, 8);
            v += __shfl_xor_sync(0xffffffffu, v, 4);
            v += __shfl_xor_sync(0xffffffffu, v, 2);
            v += __shfl_xor_sync(0xffffffffu, v, 1);
            if (lane == b) res = v;
        }
        if (lane < 8)
            g_p[((size_t)cs * NROWS + r0 + r) * BSZ + b0 + lane] = res;
    }
}

// ---------------------------------------------------------------------------
// Kernel 2: combine col-split partials + RoPE.
// ---------------------------------------------------------------------------
__global__ void k_fuse(const float* __restrict__ fc, const float* __restrict__ fs)
{
    const int t = blockIdx.x * blockDim.x + threadIdx.x;
    if (t < 32768) {                       // q pairs
        const int b = t >> 11, j = t & 2047;
        const int row = 2 * j;
        const float a  = g_p[(size_t)row * BSZ + b] + g_p[((size_t)NROWS + row) * BSZ + b];
        const float bb = g_p[(size_t)(row + 1) * BSZ + b] + g_p[((size_t)NROWS + row + 1) * BSZ + b];
        const float c = fc[j & 63], s = fs[j & 63];
        g_q[(size_t)b * DIM + row]     = a * c - bb * s;
        g_q[(size_t)b * DIM + row + 1] = a * s + bb * c;
    } else if (t < 40960) {                // k pairs
        const int u = t - 32768;
        const int b = u >> 9, j = u & 511;
        const int row = 4096 + 2 * j;
        const float a  = g_p[(size_t)row * BSZ + b] + g_p[((size_t)NROWS + row) * BSZ + b];
        const float bb = g_p[(size_t)(row + 1) * BSZ + b] + g_p[((size_t)NROWS + row + 1) * BSZ + b];
        const float c = fc[j & 63], s = fs[j & 63];
        g_k[(size_t)b * KVROW + 2 * j]     = a * c - bb * s;
        g_k[(size_t)b * KVROW + 2 * j + 1] = a * s + bb * c;
    } else if (t < 57344) {                // v elements
        const int u = t - 40960;
        const int b = u >> 10, e = u & 1023;
        const int row = 5120 + e;
        g_v[(size_t)b * KVROW + e] =
            g_p[(size_t)row * BSZ + b] + g_p[((size_t)NROWS + row) * BSZ + b];
    }
}

// ---------------------------------------------------------------------------
// Kernel 3: split-KV attention partials, packed-math version.
// sc transposed to [SCHUNK][4] so a score row is one LDS.128/STS.128.
// ---------------------------------------------------------------------------
__global__ void __launch_bounds__(256) k_attn(
    const float* __restrict__ cache_k,
    const float* __restrict__ cache_v,
    const int*   __restrict__ sp_ptr)
{
    const int split = blockIdx.x;
    const int hk    = blockIdx.y;
    const int b     = blockIdx.z;
    const int sp    = load_sp(sp_ptr);
    const int pos0  = split * SCHUNK;
    const int tid   = threadIdx.x;
    const int lane  = tid & 31;
    const int warp  = tid >> 5;
    const bool pure = (pos0 + SCHUNK <= sp);

    __shared__ __align__(16) float sc[SCHUNK][4];   // [pos][head]
    __shared__ float4 red4[8][4][32];
    __shared__ float  redm[4][8];
    __shared__ float  redl[4][8];
    __shared__ float  fm[4];

    // q fragments as packed pairs: head j, dims [lane*4 .. lane*4+3]
    ull qp[4][2];
#pragma unroll
    for (int j = 0; j < 4; j++) {
        const ulonglong2 q2 = *reinterpret_cast<const ulonglong2*>(
            g_q + (size_t)b * DIM + (hk * 4 + j) * HD + lane * 4);
        qp[j][0] = q2.x; qp[j][1] = q2.y;
    }

    // ---- Phase A: scores + running per-head max ----
    const size_t kb = (size_t)b * MSL * KVROW + (size_t)hk * HD;
    float lmax = -1e30f;                      // head = lane & 3
    if (pure) {
        const float* kp = cache_k + kb + (size_t)pos0 * KVROW + lane * 4;
        for (int p = warp; p < SCHUNK; p += 32) {
            const ulonglong2 kA = *reinterpret_cast<const ulonglong2*>(kp + (size_t)(p     ) * KVROW);
            const ulonglong2 kB = *reinterpret_cast<const ulonglong2*>(kp + (size_t)(p +  8) * KVROW);
            const ulonglong2 kC = *reinterpret_cast<const ulonglong2*>(kp + (size_t)(p + 16) * KVROW);
            const ulonglong2 kD = *reinterpret_cast<const ulonglong2*>(kp + (size_t)(p + 24) * KVROW);
            const float cA = dot4p(kA, qp, lane) * SCALE;
            const float cB = dot4p(kB, qp, lane) * SCALE;
            const float cC = dot4p(kC, qp, lane) * SCALE;
            const float cD = dot4p(kD, qp, lane) * SCALE;
            if (lane < 4) {
                sc[p     ][lane] = cA;
                sc[p +  8][lane] = cB;
                sc[p + 16][lane] = cC;
                sc[p + 24][lane] = cD;
            }
            lmax = fmaxf(lmax, fmaxf(fmaxf(cA, cB), fmaxf(cC, cD)));
        }
    } else {
        for (int p = warp; p < SCHUNK; p += 8) {
            const int pos = pos0 + p;
            ulonglong2 k2;
            if (pos < sp)
                k2 = *reinterpret_cast<const ulonglong2*>(
                    cache_k + kb + (size_t)pos * KVROW + lane * 4);
            else if (pos == sp)
                k2 = *reinterpret_cast<const ulonglong2*>(
                    g_k + (b * NKV + hk) * HD + lane * 4);
            else
                k2 = make_ulonglong2(0ull, 0ull);
            const float cc  = dot4p(k2, qp, lane) * SCALE;
            const float val = (pos <= sp) ? cc : -1e30f;
            if (lane < 4) sc[p][lane] = val;
            lmax = fmaxf(lmax, val);
        }
    }
    if (lane < 4) redm[lane][warp] = lmax;
    __syncthreads();
    if (tid < 4) {
        float m = redm[tid][0];
#pragma unroll
        for (int w = 1; w < 8; w++) m = fmaxf(m, redm[tid][w]);
        fm[tid] = m;
    }
    __syncthreads();

    // ---- exp + row-sum (row = one LDS.128 / STS.128) ----
    const float f0 = fm[0], f1 = fm[1], f2 = fm[2], f3 = fm[3];
    float l0 = 0.f, l1 = 0.f, l2 = 0.f, l3 = 0.f;
    for (int p = tid; p < SCHUNK; p += 256) {
        float4 s4 = *reinterpret_cast<float4*>(sc[p]);
        s4.x = __expf(s4.x - f0);
        s4.y = __expf(s4.y - f1);
        s4.z = __expf(s4.z - f2);
        s4.w = __expf(s4.w - f3);
        *reinterpret_cast<float4*>(sc[p]) = s4;
        l0 += s4.x; l1 += s4.y; l2 += s4.z; l3 += s4.w;
    }
    {
        float v0 = l0, v1 = l1, v2 = l2, v3 = l3;
        const float vv = red4x(v0, v1, v2, v3, lane);   // lane holds head lane&3 sum
        if (lane < 4) redl[lane][warp] = vv;
    }
    __syncthreads();

    const size_t pi = (size_t)(b * NKV + hk) * NSPLIT + split;
    if (tid < 4) {
        float s = 0.f;
#pragma unroll
        for (int w = 0; w < 8; w++) s += redl[tid][w];
        g_m[pi * 4 + tid] = fm[tid];
        g_l[pi * 4 + tid] = s;
    }
    __syncthreads();

    // ---- Phase C: packed V stream ----
    ulonglong2 a0 = {0,0}, a1 = {0,0}, a2 = {0,0}, a3 = {0,0};
    const float* vb = cache_v + (size_t)b * MSL * KVROW + (size_t)hk * HD + lane * 4;
#define ACCP(PP, V2)                                                          \
    {   const float4 pr = *reinterpret_cast<const float4*>(sc[PP]);           \
        const ull pp0 = fpack2(pr.x, pr.x);                                   \
        const ull pp1 = fpack2(pr.y, pr.y);                                   \
        const ull pp2 = fpack2(pr.z, pr.z);                                   \
        const ull pp3 = fpack2(pr.w, pr.w);                                   \
        a0.x = ffma2(pp0, (V2).x, a0.x); a0.y = ffma2(pp0, (V2).y, a0.y);     \
        a1.x = ffma2(pp1, (V2).x, a1.x); a1.y = ffma2(pp1, (V2).y, a1.y);     \
        a2.x = ffma2(pp2, (V2).x, a2.x); a2.y = ffma2(pp2, (V2).y, a2.y);     \
        a3.x = ffma2(pp3, (V2).x, a3.x); a3.y = ffma2(pp3, (V2).y, a3.y); }
    if (pure) {
        const float* vp = vb + (size_t)pos0 * KVROW;
        for (int p = warp; p < SCHUNK; p += 32) {
            const ulonglong2 vA = *reinterpret_cast<const ulonglong2*>(vp + (size_t)(p     ) * KVROW);
            const ulonglong2 vB = *reinterpret_cast<const ulonglong2*>(vp + (size_t)(p +  8) * KVROW);
            const ulonglong2 vC = *reinterpret_cast<const ulonglong2*>(vp + (size_t)(p + 16) * KVROW);
            const ulonglong2 vD = *reinterpret_cast<const ulonglong2*>(vp + (size_t)(p + 24) * KVROW);
            ACCP(p,      vA);
            ACCP(p +  8, vB);
            ACCP(p + 16, vC);
            ACCP(p + 24, vD);
        }
    } else {
        const ulonglong2 gv2 = *reinterpret_cast<const ulonglong2*>(
            g_v + (b * NKV + hk) * HD + lane * 4);
        for (int p = warp; p < SCHUNK; p += 8) {
            const int pos = pos0 + p;
            const ulonglong2 v2 = (pos == sp) ? gv2
                : *reinterpret_cast<const ulonglong2*>(vb + (size_t)pos * KVROW);
            ACCP(p, v2);
        }
    }
#undef ACCP
    red4[warp][0][lane] = make_float4(ull_lo(a0.x), ull_hi(a0.x), ull_lo(a0.y), ull_hi(a0.y));
    red4[warp][1][lane] = make_float4(ull_lo(a1.x), ull_hi(a1.x), ull_lo(a1.y), ull_hi(a1.y));
    red4[warp][2][lane] = make_float4(ull_lo(a2.x), ull_hi(a2.x), ull_lo(a2.y), ull_hi(a2.y));
    red4[warp][3][lane] = make_float4(ull_lo(a3.x), ull_hi(a3.x), ull_lo(a3.y), ull_hi(a3.y));
    __syncthreads();

    const float* redf = reinterpret_cast<const float*>(red4);
    float* op = g_op + pi * 4 * HD;
    for (int o = tid; o < 4 * HD; o += 256) {
        float s = 0.f;
#pragma unroll
        for (int w = 0; w < 8; w++) s += redf[w * 512 + o];
        op[o] = s;
    }
}

// ---------------------------------------------------------------------------
// Kernel 4: combine split partials into g_attn.
// ---------------------------------------------------------------------------
__global__ void k_combine()
{
    const int bh = blockIdx.x;
    const int d  = threadIdx.x;
    const int b  = bh >> 5, h = bh & 31;
    const int hk = h >> 2, j = h & 3;
    const int base = (b * NKV + hk) * NSPLIT;

    float M = -1e30f;
#pragma unroll
    for (int s = 0; s < NSPLIT; s++) M = fmaxf(M, g_m[(base + s) * 4 + j]);
    float den = 0.f, o = 0.f;
#pragma unroll
    for (int s = 0; s < NSPLIT; s++) {
        const float w = __expf(g_m[(base + s) * 4 + j] - M);
        den += g_l[(base + s) * 4 + j] * w;
        o   += g_op[((size_t)(base + s) * 4 + j) * HD + d] * w;
    }
    g_attn[b * DIM + h * HD + d] = o / den;
}

// ---------------------------------------------------------------------------
// Kernel 5: output GEMV, c-loop unrolled x2.
// ---------------------------------------------------------------------------
__global__ void __launch_bounds__(256, 3) k_gemv_out(
    const float* __restrict__ wo)
{
    const int warp = threadIdx.x >> 5;
    const int lane = threadIdx.x & 31;
    const int cs   = blockIdx.x & 1;
    const int bh   = (blockIdx.x >> 1) & 1;
    const int rb   = blockIdx.x >> 2;
    const int r0   = rb * 16 + warp * 2;
    const int b0   = bh * 8;
    const int c0   = cs * 2048;

    const float* w0p = wo + (size_t)(r0 + 0) * DIM + c0;
    const float* w1p = wo + (size_t)(r0 + 1) * DIM + c0;
    const float* xp  = g_attn + (size_t)b0 * DIM + c0;

    ull acc[2][8];
#pragma unroll
    for (int r = 0; r < 2; r++)
#pragma unroll
        for (int b = 0; b < 8; b++) acc[r][b] = 0ull;

    const int off = lane * 4;
    for (int c = 0; c < 2048; c += 256) {
        const ulonglong2 w0a = *reinterpret_cast<const ulonglong2*>(w0p + c + off);
        const ulonglong2 w1a = *reinterpret_cast<const ulonglong2*>(w1p + c + off);
        const ulonglong2 w0b = *reinterpret_cast<const ulonglong2*>(w0p + c + 128 + off);
        const ulonglong2 w1b = *reinterpret_cast<const ulonglong2*>(w1p + c + 128 + off);
#pragma unroll
        for (int b = 0; b < 8; b++) {
            const ulonglong2 xa =
                *reinterpret_cast<const ulonglong2*>(xp + (size_t)b * DIM + c + off);
            const ulonglong2 xb =
                *reinterpret_cast<const ulonglong2*>(xp + (size_t)b * DIM + c + 128 + off);
            acc[0][b] = ffma2(w0a.x, xa.x, acc[0][b]);
            acc[0][b] = ffma2(w0a.y, xa.y, acc[0][b]);
            acc[1][b] = ffma2(w1a.x, xa.x, acc[1][b]);
            acc[1][b] = ffma2(w1a.y, xa.y, acc[1][b]);
            acc[0][b] = ffma2(w0b.x, xb.x, acc[0][b]);
            acc[0][b] = ffma2(w0b.y, xb.y, acc[0][b]);
            acc[1][b] = ffma2(w1b.x, xb.x, acc[1][b]);
            acc[1][b] = ffma2(w1b.y, xb.y, acc[1][b]);
        }
    }

#pragma unroll
    for (int r = 0; r < 2; r++) {
        float res = 0.f;
#pragma unroll
        for (int b = 0; b < 8; b++) {
            float v = hsum2(acc[r][b]);
            v += __shfl_xor_sync(0xffffffffu, v, 16);
            v += __shfl_xor_sync(0xffffffffu, v, 8);
            v += __shfl_xor_sync(0xffffffffu, v, 4);
            v += __shfl_xor_sync(0xffffffffu, v, 2);
            v += __shfl_xor_sync(0xffffffffu, v, 1);
            if (lane == b) res = v;
        }
        if (lane < 8)
            g_po[((size_t)cs * DIM + r0 + r) * BSZ + b0 + lane] = res;
    }
}

// ---------------------------------------------------------------------------
// Kernel 6: combine output col-split partials -> d_out.
// ---------------------------------------------------------------------------
__global__ void k_ocomb(float* __restrict__ out)
{
    const int t = blockIdx.x * blockDim.x + threadIdx.x;
    const int b = t >> 12, row = t & 4095;
    out[(size_t)b * DIM + row] =
        g_po[(size_t)row * BSZ + b] + g_po[((size_t)DIM + row) * BSZ + b];
}

// ---------------------------------------------------------------------------
extern "C" void kernel_launch(void* const* d_in, const int* in_sizes, int n_in,
                              void* d_out, int out_size)
{
    const float* x  = (const float*)d_in[0];
    const float* wq = (const float*)d_in[1];
    const float* wk = (const float*)d_in[2];
    const float* wv = (const float*)d_in[3];
    const float* wo = (const float*)d_in[4];
    const float* ck = (const float*)d_in[5];
    const float* cv = (const float*)d_in[6];
    const float* fc = (const float*)d_in[7];
    const float* fs = (const float*)d_in[8];
    const int*   sp = (const int*)d_in[9];
    float* out = (float*)d_out;

    k_gemv_qkv<<<1536, 256>>>(x, wq, wk, wv);
    k_fuse<<<224, 256>>>(fc, fs);
    dim3 ag(NSPLIT, NKV, BSZ);
    k_attn<<<ag, 256>>>(ck, cv, sp);
    k_combine<<<BSZ * NH, HD>>>();
    k_gemv_out<<<1024, 256>>>(wo);
    k_ocomb<<<256, 256>>>(out);
}

// round 12
// speedup vs baseline: 1.0106x; 1.0106x over previous
#include <cuda_runtime.h>
#include <cuda_bf16.h>
#include <cstdint>

// Problem constants (fixed by the dataset).
#define BSZ     16
#define DIM     4096
#define NH      32
#define NKV     8
#define HD      128
#define MSL     4096
#define NSPLIT  16
#define SCHUNK  256          // MSL / NSPLIT
#define KVROW   (NKV * HD)   // 1024 floats per cache position
#define SCALE   0.08838834764831845f   // 1/sqrt(128)
#define NROWS   6144         // 4096 q + 1024 k + 1024 v

// ---------------------------------------------------------------------------
// Scratch
// ---------------------------------------------------------------------------
__device__ __align__(16) float g_q[BSZ * NH * HD];
__device__ __align__(16) float g_k[BSZ * NKV * HD];
__device__ __align__(16) float g_v[BSZ * NKV * HD];
__device__ __align__(16) float g_p [2 * NROWS * BSZ];
__device__ __align__(16) float g_po[2 * DIM   * BSZ];
__device__ __align__(16) float g_op[BSZ * NKV * NSPLIT * 4 * HD];
__device__ float g_m[BSZ * NKV * NSPLIT * 4];
__device__ float g_l[BSZ * NKV * NSPLIT * 4];
__device__ __align__(16) float g_attn[BSZ * DIM];

__device__ __forceinline__ int load_sp(const int* p) {
    int v = *p;
    if (v < 0 || v >= 1000000) v = (int)__int_as_float(v);
    return v;
}

typedef unsigned long long ull;

__device__ __forceinline__ ull ffma2(ull a, ull b, ull c) {
    ull d;
    asm("fma.rn.f32x2 %0, %1, %2, %3;" : "=l"(d) : "l"(a), "l"(b), "l"(c));
    return d;
}
__device__ __forceinline__ ull fmul2(ull a, ull b) {
    ull d;
    asm("mul.rn.f32x2 %0, %1, %2;" : "=l"(d) : "l"(a), "l"(b));
    return d;
}
__device__ __forceinline__ float ull_lo(ull v) {
    return __uint_as_float((unsigned)(v & 0xffffffffull));
}
__device__ __forceinline__ float ull_hi(ull v) {
    return __uint_as_float((unsigned)(v >> 32));
}
__device__ __forceinline__ float hsum2(ull v) { return ull_lo(v) + ull_hi(v); }

// 9-shuffle joint reduce of 4 per-lane partials over 32 lanes;
// every lane ends with the full sum of value (lane & 3).
__device__ __forceinline__ float red4x(float d0, float d1, float d2, float d3, int lane)
{
    d0 += __shfl_xor_sync(0xffffffffu, d0, 1);
    d1 += __shfl_xor_sync(0xffffffffu, d1, 1);
    d2 += __shfl_xor_sync(0xffffffffu, d2, 1);
    d3 += __shfl_xor_sync(0xffffffffu, d3, 1);
    float aa = (lane & 1) ? d1 : d0;
    float bb = (lane & 1) ? d3 : d2;
    aa += __shfl_xor_sync(0xffffffffu, aa, 2);
    bb += __shfl_xor_sync(0xffffffffu, bb, 2);
    float cc = (lane & 2) ? bb : aa;
    cc += __shfl_xor_sync(0xffffffffu, cc, 4);
    cc += __shfl_xor_sync(0xffffffffu, cc, 8);
    cc += __shfl_xor_sync(0xffffffffu, cc, 16);
    return cc;
}

// Two interleaved joint reduces of 4 values over 16-lane groups (xor 1,2,4,8).
// Each lane ends with head (lane&3)'s sum for its own 16-lane group.
__device__ __forceinline__ void red4x16_2(
    float dA0, float dA1, float dA2, float dA3,
    float dB0, float dB1, float dB2, float dB3,
    int lane, float& outA, float& outB)
{
    dA0 += __shfl_xor_sync(0xffffffffu, dA0, 1);
    dB0 += __shfl_xor_sync(0xffffffffu, dB0, 1);
    dA1 += __shfl_xor_sync(0xffffffffu, dA1, 1);
    dB1 += __shfl_xor_sync(0xffffffffu, dB1, 1);
    dA2 += __shfl_xor_sync(0xffffffffu, dA2, 1);
    dB2 += __shfl_xor_sync(0xffffffffu, dB2, 1);
    dA3 += __shfl_xor_sync(0xffffffffu, dA3, 1);
    dB3 += __shfl_xor_sync(0xffffffffu, dB3, 1);
    float aA = (lane & 1) ? dA1 : dA0;
    float bA = (lane & 1) ? dA3 : dA2;
    float aB = (lane & 1) ? dB1 : dB0;
    float bB = (lane & 1) ? dB3 : dB2;
    aA += __shfl_xor_sync(0xffffffffu, aA, 2);
    aB += __shfl_xor_sync(0xffffffffu, aB, 2);
    bA += __shfl_xor_sync(0xffffffffu, bA, 2);
    bB += __shfl_xor_sync(0xffffffffu, bB, 2);
    float cA = (lane & 2) ? bA : aA;
    float cB = (lane & 2) ? bB : aB;
    cA += __shfl_xor_sync(0xffffffffu, cA, 4);
    cB += __shfl_xor_sync(0xffffffffu, cB, 4);
    cA += __shfl_xor_sync(0xffffffffu, cA, 8);
    cB += __shfl_xor_sync(0xffffffffu, cB, 8);
    outA = cA; outB = cB;
}

// ---------------------------------------------------------------------------
// Kernel 1: QKV GEMV (unchanged from R10).
// ---------------------------------------------------------------------------
__global__ void __launch_bounds__(256, 3) k_gemv_qkv(
    const float* __restrict__ x,
    const float* __restrict__ wq,
    const float* __restrict__ wk,
    const float* __restrict__ wv)
{
    const int warp = threadIdx.x >> 5;
    const int lane = threadIdx.x & 31;
    const int cs   = blockIdx.x & 1;
    const int bh   = (blockIdx.x >> 1) & 1;
    const int rb   = blockIdx.x >> 2;
    const int r0   = rb * 16 + warp * 2;
    const int b0   = bh * 8;
    const int c0   = cs * 2048;

    const float* W; int rbase;
    if (r0 < 4096)      { W = wq; rbase = r0;        }
    else if (r0 < 5120) { W = wk; rbase = r0 - 4096; }
    else                { W = wv; rbase = r0 - 5120; }

    const float* w0p = W + (size_t)(rbase + 0) * DIM + c0;
    const float* w1p = W + (size_t)(rbase + 1) * DIM + c0;
    const float* xp  = x + (size_t)b0 * DIM + c0;

    ull acc[2][8];
#pragma unroll
    for (int r = 0; r < 2; r++)
#pragma unroll
        for (int b = 0; b < 8; b++) acc[r][b] = 0ull;

    const int off = lane * 4;
    for (int c = 0; c < 2048; c += 256) {
        const ulonglong2 w0a = *reinterpret_cast<const ulonglong2*>(w0p + c + off);
        const ulonglong2 w1a = *reinterpret_cast<const ulonglong2*>(w1p + c + off);
        const ulonglong2 w0b = *reinterpret_cast<const ulonglong2*>(w0p + c + 128 + off);
        const ulonglong2 w1b = *reinterpret_cast<const ulonglong2*>(w1p + c + 128 + off);
#pragma unroll
        for (int b = 0; b < 8; b++) {
            const ulonglong2 xa =
                *reinterpret_cast<const ulonglong2*>(xp + (size_t)b * DIM + c + off);
            const ulonglong2 xb =
                *reinterpret_cast<const ulonglong2*>(xp + (size_t)b * DIM + c + 128 + off);
            acc[0][b] = ffma2(w0a.x, xa.x, acc[0][b]);
            acc[0][b] = ffma2(w0a.y, xa.y, acc[0][b]);
            acc[1][b] = ffma2(w1a.x, xa.x, acc[1][b]);
            acc[1][b] = ffma2(w1a.y, xa.y, acc[1][b]);
            acc[0][b] = ffma2(w0b.x, xb.x, acc[0][b]);
            acc[0][b] = ffma2(w0b.y, xb.y, acc[0][b]);
            acc[1][b] = ffma2(w1b.x, xb.x, acc[1][b]);
            acc[1][b] = ffma2(w1b.y, xb.y, acc[1][b]);
        }
    }

#pragma unroll
    for (int r = 0; r < 2; r++) {
        float res = 0.f;
#pragma unroll
        for (int b = 0; b < 8; b++) {
            float v = hsum2(acc[r][b]);
            v += __shfl_xor_sync(0xffffffffu, v, 16);
            v += __shfl_xor_sync(0xffffffffu, v, 8);
            v += __shfl_xor_sync(0xffffffffu, v, 4);
            v += __shfl_xor_sync(0xffffffffu, v, 2);
            v += __shfl_xor_sync(0xffffffffu, v, 1);
            if (lane == b) res = v;
        }
        if (lane < 8)
            g_p[((size_t)cs * NROWS + r0 + r) * BSZ + b0 + lane] = res;
    }
}

// ---------------------------------------------------------------------------
// Kernel 2: combine col-split partials + RoPE (unchanged).
// ---------------------------------------------------------------------------
__global__ void k_fuse(const float* __restrict__ fc, const float* __restrict__ fs)
{
    const int t = blockIdx.x * blockDim.x + threadIdx.x;
    if (t < 32768) {                       // q pairs
        const int b = t >> 11, j = t & 2047;
        const int row = 2 * j;
        const float a  = g_p[(size_t)row * BSZ + b] + g_p[((size_t)NROWS + row) * BSZ + b];
        const float bb = g_p[(size_t)(row + 1) * BSZ + b] + g_p[((size_t)NROWS + row + 1) * BSZ + b];
        const float c = fc[j & 63], s = fs[j & 63];
        g_q[(size_t)b * DIM + row]     = a * c - bb * s;
        g_q[(size_t)b * DIM + row + 1] = a * s + bb * c;
    } else if (t < 40960) {                // k pairs
        const int u = t - 32768;
        const int b = u >> 9, j = u & 511;
        const int row = 4096 + 2 * j;
        const float a  = g_p[(size_t)row * BSZ + b] + g_p[((size_t)NROWS + row) * BSZ + b];
        const float bb = g_p[(size_t)(row + 1) * BSZ + b] + g_p[((size_t)NROWS + row + 1) * BSZ + b];
        const float c = fc[j & 63], s = fs[j & 63];
        g_k[(size_t)b * KVROW + 2 * j]     = a * c - bb * s;
        g_k[(size_t)b * KVROW + 2 * j + 1] = a * s + bb * c;
    } else if (t < 57344) {                // v elements
        const int u = t - 40960;
        const int b = u >> 10, e = u & 1023;
        const int row = 5120 + e;
        g_v[(size_t)b * KVROW + e] =
            g_p[(size_t)row * BSZ + b] + g_p[((size_t)NROWS + row) * BSZ + b];
    }
}

// ---------------------------------------------------------------------------
// Kernel 3: split-KV attention partials.
// Phase A: 16-lane-per-position dot (2 positions/warp-iter, 4 shuffles/pos,
//          chain depth 4, two reduce trees interleaved).
// Phase C: scalar-FFMA V stream with transposed sc.
// ---------------------------------------------------------------------------
__global__ void __launch_bounds__(256) k_attn(
    const float* __restrict__ cache_k,
    const float* __restrict__ cache_v,
    const int*   __restrict__ sp_ptr)
{
    const int split = blockIdx.x;
    const int hk    = blockIdx.y;
    const int b     = blockIdx.z;
    const int sp    = load_sp(sp_ptr);
    const int pos0  = split * SCHUNK;
    const int tid   = threadIdx.x;
    const int lane  = tid & 31;
    const int warp  = tid >> 5;
    const bool pure = (pos0 + SCHUNK <= sp);

    __shared__ __align__(16) float sc[SCHUNK][4];   // [pos][head]
    __shared__ float4 red4[8][4][32];
    __shared__ float  redm[4][8];
    __shared__ float  redl[4][8];
    __shared__ float  fm[4];

    const size_t kb = (size_t)b * MSL * KVROW + (size_t)hk * HD;
    float lmax = -1e30f;                      // head = lane & 3

    // ---- Phase A: scores + running per-head max ----
    if (pure) {
        // 16 lanes per position, 8 dims per lane.
        const int sub  = lane >> 4;           // which of the 2 positions
        const int doff = (lane & 15) * 8;     // dim offset for this lane
        ull qp[4][4];
#pragma unroll
        for (int j = 0; j < 4; j++) {
            const float* qb = g_q + (size_t)b * DIM + (hk * 4 + j) * HD + doff;
            const ulonglong2 qa = *reinterpret_cast<const ulonglong2*>(qb);
            const ulonglong2 qc = *reinterpret_cast<const ulonglong2*>(qb + 4);
            qp[j][0] = qa.x; qp[j][1] = qa.y; qp[j][2] = qc.x; qp[j][3] = qc.y;
        }
        const float* kp = cache_k + kb + (size_t)pos0 * KVROW + doff;
        const int pbase = warp * 2 + sub;
#pragma unroll 2
        for (int r = 0; r < 16; r += 2) {
            const int pA = r * 16 + pbase;
            const int pB = pA + 16;
            const ulonglong2 kA0 = *reinterpret_cast<const ulonglong2*>(kp + (size_t)pA * KVROW);
            const ulonglong2 kA1 = *reinterpret_cast<const ulonglong2*>(kp + (size_t)pA * KVROW + 4);
            const ulonglong2 kB0 = *reinterpret_cast<const ulonglong2*>(kp + (size_t)pB * KVROW);
            const ulonglong2 kB1 = *reinterpret_cast<const ulonglong2*>(kp + (size_t)pB * KVROW + 4);
            float dA[4], dB[4];
#pragma unroll
            for (int j = 0; j < 4; j++) {
                ull tA = fmul2(kA0.x, qp[j][0]);
                tA = ffma2(kA0.y, qp[j][1], tA);
                tA = ffma2(kA1.x, qp[j][2], tA);
                tA = ffma2(kA1.y, qp[j][3], tA);
                dA[j] = hsum2(tA);
                ull tB = fmul2(kB0.x, qp[j][0]);
                tB = ffma2(kB0.y, qp[j][1], tB);
                tB = ffma2(kB1.x, qp[j][2], tB);
                tB = ffma2(kB1.y, qp[j][3], tB);
                dB[j] = hsum2(tB);
            }
            float cA, cB;
            red4x16_2(dA[0], dA[1], dA[2], dA[3],
                      dB[0], dB[1], dB[2], dB[3], lane, cA, cB);
            cA *= SCALE; cB *= SCALE;
            if ((lane & 12) == 0) {
                sc[pA][lane & 3] = cA;
                sc[pB][lane & 3] = cB;
            }
            lmax = fmaxf(lmax, fmaxf(cA, cB));
        }
        // fold the two 16-lane groups' maxima together
        lmax = fmaxf(lmax, __shfl_xor_sync(0xffffffffu, lmax, 16));
    } else {
        // boundary split: scalar per-position path (runs on 128 of 2048 blocks)
        float4 ql[4];
#pragma unroll
        for (int j = 0; j < 4; j++)
            ql[j] = *reinterpret_cast<const float4*>(
                g_q + (size_t)b * DIM + (hk * 4 + j) * HD + lane * 4);
        for (int p = warp; p < SCHUNK; p += 8) {
            const int pos = pos0 + p;
            float4 k4;
            if (pos < sp)
                k4 = *reinterpret_cast<const float4*>(
                    cache_k + kb + (size_t)pos * KVROW + lane * 4);
            else if (pos == sp)
                k4 = *reinterpret_cast<const float4*>(
                    g_k + (b * NKV + hk) * HD + lane * 4);
            else
                k4 = make_float4(0.f, 0.f, 0.f, 0.f);
            const float d0 = k4.x*ql[0].x + k4.y*ql[0].y + k4.z*ql[0].z + k4.w*ql[0].w;
            const float d1 = k4.x*ql[1].x + k4.y*ql[1].y + k4.z*ql[1].z + k4.w*ql[1].w;
            const float d2 = k4.x*ql[2].x + k4.y*ql[2].y + k4.z*ql[2].z + k4.w*ql[2].w;
            const float d3 = k4.x*ql[3].x + k4.y*ql[3].y + k4.z*ql[3].z + k4.w*ql[3].w;
            const float cc  = red4x(d0, d1, d2, d3, lane) * SCALE;
            const float val = (pos <= sp) ? cc : -1e30f;
            if (lane < 4) sc[p][lane] = val;
            lmax = fmaxf(lmax, val);
        }
    }
    if (lane < 4) redm[lane][warp] = lmax;
    __syncthreads();
    if (tid < 4) {
        float m = redm[tid][0];
#pragma unroll
        for (int w = 1; w < 8; w++) m = fmaxf(m, redm[tid][w]);
        fm[tid] = m;
    }
    __syncthreads();

    // ---- exp + row-sum (row = one LDS.128 / STS.128) ----
    const float f0 = fm[0], f1 = fm[1], f2 = fm[2], f3 = fm[3];
    float l0 = 0.f, l1 = 0.f, l2 = 0.f, l3 = 0.f;
    for (int p = tid; p < SCHUNK; p += 256) {
        float4 s4 = *reinterpret_cast<float4*>(sc[p]);
        s4.x = __expf(s4.x - f0);
        s4.y = __expf(s4.y - f1);
        s4.z = __expf(s4.z - f2);
        s4.w = __expf(s4.w - f3);
        *reinterpret_cast<float4*>(sc[p]) = s4;
        l0 += s4.x; l1 += s4.y; l2 += s4.z; l3 += s4.w;
    }
    {
        const float vv = red4x(l0, l1, l2, l3, lane);
        if (lane < 4) redl[lane][warp] = vv;
    }
    __syncthreads();

    const size_t pi = (size_t)(b * NKV + hk) * NSPLIT + split;
    if (tid < 4) {
        float s = 0.f;
#pragma unroll
        for (int w = 0; w < 8; w++) s += redl[tid][w];
        g_m[pi * 4 + tid] = fm[tid];
        g_l[pi * 4 + tid] = s;
    }
    __syncthreads();

    // ---- Phase C: scalar-FFMA V stream ----
    float4 a0 = {0,0,0,0}, a1 = {0,0,0,0}, a2 = {0,0,0,0}, a3 = {0,0,0,0};
    const float* vb = cache_v + (size_t)b * MSL * KVROW + (size_t)hk * HD + lane * 4;
#define ACC4(PP, V4)                                                          \
    {   const float4 pr = *reinterpret_cast<const float4*>(sc[PP]);           \
        a0.x = fmaf(pr.x, (V4).x, a0.x); a0.y = fmaf(pr.x, (V4).y, a0.y);     \
        a0.z = fmaf(pr.x, (V4).z, a0.z); a0.w = fmaf(pr.x, (V4).w, a0.w);     \
        a1.x = fmaf(pr.y, (V4).x, a1.x); a1.y = fmaf(pr.y, (V4).y, a1.y);     \
        a1.z = fmaf(pr.y, (V4).z, a1.z); a1.w = fmaf(pr.y, (V4).w, a1.w);     \
        a2.x = fmaf(pr.z, (V4).x, a2.x); a2.y = fmaf(pr.z, (V4).y, a2.y);     \
        a2.z = fmaf(pr.z, (V4).z, a2.z); a2.w = fmaf(pr.z, (V4).w, a2.w);     \
        a3.x = fmaf(pr.w, (V4).x, a3.x); a3.y = fmaf(pr.w, (V4).y, a3.y);     \
        a3.z = fmaf(pr.w, (V4).z, a3.z); a3.w = fmaf(pr.w, (V4).w, a3.w); }
    if (pure) {
        const float* vp = vb + (size_t)pos0 * KVROW;
        for (int p = warp; p < SCHUNK; p += 32) {
            const float4 vA = *reinterpret_cast<const float4*>(vp + (size_t)(p     ) * KVROW);
            const float4 vB = *reinterpret_cast<const float4*>(vp + (size_t)(p +  8) * KVROW);
            const float4 vC = *reinterpret_cast<const float4*>(vp + (size_t)(p + 16) * KVROW);
            const float4 vD = *reinterpret_cast<const float4*>(vp + (size_t)(p + 24) * KVROW);
            ACC4(p,      vA);
            ACC4(p +  8, vB);
            ACC4(p + 16, vC);
            ACC4(p + 24, vD);
        }
    } else {
        const float4 gv4 = *reinterpret_cast<const float4*>(
            g_v + (b * NKV + hk) * HD + lane * 4);
        for (int p = warp; p < SCHUNK; p += 8) {
            const int pos = pos0 + p;
            const float4 v4 = (pos == sp) ? gv4
                : *reinterpret_cast<const float4*>(vb + (size_t)pos * KVROW);
            ACC4(p, v4);
        }
    }
#undef ACC4
    red4[warp][0][lane] = a0;
    red4[warp][1][lane] = a1;
    red4[warp][2][lane] = a2;
    red4[warp][3][lane] = a3;
    __syncthreads();

    const float* redf = reinterpret_cast<const float*>(red4);
    float* op = g_op + pi * 4 * HD;
    for (int o = tid; o < 4 * HD; o += 256) {
        float s = 0.f;
#pragma unroll
        for (int w = 0; w < 8; w++) s += redf[w * 512 + o];
        op[o] = s;
    }
}

// ---------------------------------------------------------------------------
// Kernel 4: combine split partials into g_attn (unchanged).
// ---------------------------------------------------------------------------
__global__ void k_combine()
{
    const int bh = blockIdx.x;
    const int d  = threadIdx.x;
    const int b  = bh >> 5, h = bh & 31;
    const int hk = h >> 2, j = h & 3;
    const int base = (b * NKV + hk) * NSPLIT;

    float M = -1e30f;
#pragma unroll
    for (int s = 0; s < NSPLIT; s++) M = fmaxf(M, g_m[(base + s) * 4 + j]);
    float den = 0.f, o = 0.f;
#pragma unroll
    for (int s = 0; s < NSPLIT; s++) {
        const float w = __expf(g_m[(base + s) * 4 + j] - M);
        den += g_l[(base + s) * 4 + j] * w;
        o   += g_op[((size_t)(base + s) * 4 + j) * HD + d] * w;
    }
    g_attn[b * DIM + h * HD + d] = o / den;
}

// ---------------------------------------------------------------------------
// Kernel 5: output GEMV (unchanged from R10).
// ---------------------------------------------------------------------------
__global__ void __launch_bounds__(256, 3) k_gemv_out(
    const float* __restrict__ wo)
{
    const int warp = threadIdx.x >> 5;
    const int lane = threadIdx.x & 31;
    const int cs   = blockIdx.x & 1;
    const int bh   = (blockIdx.x >> 1) & 1;
    const int rb   = blockIdx.x >> 2;
    const int r0   = rb * 16 + warp * 2;
    const int b0   = bh * 8;
    const int c0   = cs * 2048;

    const float* w0p = wo + (size_t)(r0 + 0) * DIM + c0;
    const float* w1p = wo + (size_t)(r0 + 1) * DIM + c0;
    const float* xp  = g_attn + (size_t)b0 * DIM + c0;

    ull acc[2][8];
#pragma unroll
    for (int r = 0; r < 2; r++)
#pragma unroll
        for (int b = 0; b < 8; b++) acc[r][b] = 0ull;

    const int off = lane * 4;
    for (int c = 0; c < 2048; c += 256) {
        const ulonglong2 w0a = *reinterpret_cast<const ulonglong2*>(w0p + c + off);
        const ulonglong2 w1a = *reinterpret_cast<const ulonglong2*>(w1p + c + off);
        const ulonglong2 w0b = *reinterpret_cast<const ulonglong2*>(w0p + c + 128 + off);
        const ulonglong2 w1b = *reinterpret_cast<const ulonglong2*>(w1p + c + 128 + off);
#pragma unroll
        for (int b = 0; b < 8; b++) {
            const ulonglong2 xa =
                *reinterpret_cast<const ulonglong2*>(xp + (size_t)b * DIM + c + off);
            const ulonglong2 xb =
                *reinterpret_cast<const ulonglong2*>(xp + (size_t)b * DIM + c + 128 + off);
            acc[0][b] = ffma2(w0a.x, xa.x, acc[0][b]);
            acc[0][b] = ffma2(w0a.y, xa.y, acc[0][b]);
            acc[1][b] = ffma2(w1a.x, xa.x, acc[1][b]);
            acc[1][b] = ffma2(w1a.y, xa.y, acc[1][b]);
            acc[0][b] = ffma2(w0b.x, xb.x, acc[0][b]);
            acc[0][b] = ffma2(w0b.y, xb.y, acc[0][b]);
            acc[1][b] = ffma2(w1b.x, xb.x, acc[1][b]);
            acc[1][b] = ffma2(w1b.y, xb.y, acc[1][b]);
        }
    }

#pragma unroll
    for (int r = 0; r < 2; r++) {
        float res = 0.f;
#pragma unroll
        for (int b = 0; b < 8; b++) {
            float v = hsum2(acc[r][b]);
            v += __shfl_xor_sync(0xffffffffu, v, 16);
            v += __shfl_xor_sync(0xffffffffu, v, 8);
            v += __shfl_xor_sync(0xffffffffu, v, 4);
            v += __shfl_xor_sync(0xffffffffu, v, 2);
            v += __shfl_xor_sync(0xffffffffu, v, 1);
            if (lane == b) res = v;
        }
        if (lane < 8)
            g_po[((size_t)cs * DIM + r0 + r) * BSZ + b0 + lane] = res;
    }
}

// ---------------------------------------------------------------------------
// Kernel 6: combine output col-split partials -> d_out (unchanged).
// ---------------------------------------------------------------------------
__global__ void k_ocomb(float* __restrict__ out)
{
    const int t = blockIdx.x * blockDim.x + threadIdx.x;
    const int b = t >> 12, row = t & 4095;
    out[(size_t)b * DIM + row] =
        g_po[(size_t)row * BSZ + b] + g_po[((size_t)DIM + row) * BSZ + b];
}

// ---------------------------------------------------------------------------
extern "C" void kernel_launch(void* const* d_in, const int* in_sizes, int n_in,
                              void* d_out, int out_size)
{
    const float* x  = (const float*)d_in[0];
    const float* wq = (const float*)d_in[1];
    const float* wk = (const float*)d_in[2];
    const float* wv = (const float*)d_in[3];
    const float* wo = (const float*)d_in[4];
    const float* ck = (const float*)d_in[5];
    const float* cv = (const float*)d_in[6];
    const float* fc = (const float*)d_in[7];
    const float* fs = (const float*)d_in[8];
    const int*   sp = (const int*)d_in[9];
    float* out = (float*)d_out;

    k_gemv_qkv<<<1536, 256>>>(x, wq, wk, wv);
    k_fuse<<<224, 256>>>(fc, fs);
    dim3 ag(NSPLIT, NKV, BSZ);
    k_attn<<<ag, 256>>>(ck, cv, sp);
    k_combine<<<BSZ * NH, HD>>>();
    k_gemv_out<<<1024, 256>>>(wo);
    k_ocomb<<<256, 256>>>(out);
}

// round 14
// speedup vs baseline: 1.0411x; 1.0302x over previous
#include <cuda_runtime.h>
#include <cuda_bf16.h>
#include <cstdint>

// Problem constants (fixed by the dataset).
#define BSZ     16
#define DIM     4096
#define NH      32
#define NKV     8
#define HD      128
#define MSL     4096
#define NSPLIT  32
#define SCHUNK  128          // MSL / NSPLIT
#define KVROW   (NKV * HD)   // 1024 floats per cache position
#define SCALE   0.08838834764831845f   // 1/sqrt(128)
#define NROWS   6144         // 4096 q + 1024 k + 1024 v

// ---------------------------------------------------------------------------
// Scratch
// ---------------------------------------------------------------------------
__device__ __align__(16) float g_q[BSZ * NH * HD];
__device__ __align__(16) float g_k[BSZ * NKV * HD];
__device__ __align__(16) float g_v[BSZ * NKV * HD];
__device__ __align__(16) float g_p [2 * NROWS * BSZ];
__device__ __align__(16) float g_po[2 * DIM   * BSZ];
__device__ __align__(16) float g_op[BSZ * NKV * NSPLIT * 4 * HD];   // 8 MB
__device__ float g_m[BSZ * NKV * NSPLIT * 4];
__device__ float g_l[BSZ * NKV * NSPLIT * 4];
__device__ __align__(16) float g_attn[BSZ * DIM];

__device__ __forceinline__ int load_sp(const int* p) {
    int v = *p;
    if (v < 0 || v >= 1000000) v = (int)__int_as_float(v);
    return v;
}

typedef unsigned long long ull;

__device__ __forceinline__ ull ffma2(ull a, ull b, ull c) {
    ull d;
    asm("fma.rn.f32x2 %0, %1, %2, %3;" : "=l"(d) : "l"(a), "l"(b), "l"(c));
    return d;
}
__device__ __forceinline__ float ull_lo(ull v) {
    return __uint_as_float((unsigned)(v & 0xffffffffull));
}
__device__ __forceinline__ float ull_hi(ull v) {
    return __uint_as_float((unsigned)(v >> 32));
}
__device__ __forceinline__ float hsum2(ull v) { return ull_lo(v) + ull_hi(v); }

// Joint 4-head dot + 9-shuffle reduce; returns head-(lane&3) total in every lane.
__device__ __forceinline__ float dot4r(const float4 k4, const float4 ql[4], int lane)
{
    float d0 = k4.x*ql[0].x + k4.y*ql[0].y + k4.z*ql[0].z + k4.w*ql[0].w;
    float d1 = k4.x*ql[1].x + k4.y*ql[1].y + k4.z*ql[1].z + k4.w*ql[1].w;
    float d2 = k4.x*ql[2].x + k4.y*ql[2].y + k4.z*ql[2].z + k4.w*ql[2].w;
    float d3 = k4.x*ql[3].x + k4.y*ql[3].y + k4.z*ql[3].z + k4.w*ql[3].w;
    d0 += __shfl_xor_sync(0xffffffffu, d0, 1);
    d1 += __shfl_xor_sync(0xffffffffu, d1, 1);
    d2 += __shfl_xor_sync(0xffffffffu, d2, 1);
    d3 += __shfl_xor_sync(0xffffffffu, d3, 1);
    float aa = (lane & 1) ? d1 : d0;
    float bb = (lane & 1) ? d3 : d2;
    aa += __shfl_xor_sync(0xffffffffu, aa, 2);
    bb += __shfl_xor_sync(0xffffffffu, bb, 2);
    float cc = (lane & 2) ? bb : aa;
    cc += __shfl_xor_sync(0xffffffffu, cc, 4);
    cc += __shfl_xor_sync(0xffffffffu, cc, 8);
    cc += __shfl_xor_sync(0xffffffffu, cc, 16);
    return cc;
}

// ---------------------------------------------------------------------------
// Kernel 1: QKV GEMV (unchanged — R9/R12 form).
// ---------------------------------------------------------------------------
__global__ void __launch_bounds__(256, 3) k_gemv_qkv(
    const float* __restrict__ x,
    const float* __restrict__ wq,
    const float* __restrict__ wk,
    const float* __restrict__ wv)
{
    const int warp = threadIdx.x >> 5;
    const int lane = threadIdx.x & 31;
    const int cs   = blockIdx.x & 1;
    const int bh   = (blockIdx.x >> 1) & 1;
    const int rb   = blockIdx.x >> 2;
    const int r0   = rb * 16 + warp * 2;
    const int b0   = bh * 8;
    const int c0   = cs * 2048;

    const float* W; int rbase;
    if (r0 < 4096)      { W = wq; rbase = r0;        }
    else if (r0 < 5120) { W = wk; rbase = r0 - 4096; }
    else                { W = wv; rbase = r0 - 5120; }

    const float* w0p = W + (size_t)(rbase + 0) * DIM + c0;
    const float* w1p = W + (size_t)(rbase + 1) * DIM + c0;
    const float* xp  = x + (size_t)b0 * DIM + c0;

    ull acc[2][8];
#pragma unroll
    for (int r = 0; r < 2; r++)
#pragma unroll
        for (int b = 0; b < 8; b++) acc[r][b] = 0ull;

    const int off = lane * 4;
    for (int c = 0; c < 2048; c += 256) {
        const ulonglong2 w0a = *reinterpret_cast<const ulonglong2*>(w0p + c + off);
        const ulonglong2 w1a = *reinterpret_cast<const ulonglong2*>(w1p + c + off);
        const ulonglong2 w0b = *reinterpret_cast<const ulonglong2*>(w0p + c + 128 + off);
        const ulonglong2 w1b = *reinterpret_cast<const ulonglong2*>(w1p + c + 128 + off);
#pragma unroll
        for (int b = 0; b < 8; b++) {
            const ulonglong2 xa =
                *reinterpret_cast<const ulonglong2*>(xp + (size_t)b * DIM + c + off);
            const ulonglong2 xb =
                *reinterpret_cast<const ulonglong2*>(xp + (size_t)b * DIM + c + 128 + off);
            acc[0][b] = ffma2(w0a.x, xa.x, acc[0][b]);
            acc[0][b] = ffma2(w0a.y, xa.y, acc[0][b]);
            acc[1][b] = ffma2(w1a.x, xa.x, acc[1][b]);
            acc[1][b] = ffma2(w1a.y, xa.y, acc[1][b]);
            acc[0][b] = ffma2(w0b.x, xb.x, acc[0][b]);
            acc[0][b] = ffma2(w0b.y, xb.y, acc[0][b]);
            acc[1][b] = ffma2(w1b.x, xb.x, acc[1][b]);
            acc[1][b] = ffma2(w1b.y, xb.y, acc[1][b]);
        }
    }

#pragma unroll
    for (int r = 0; r < 2; r++) {
        float res = 0.f;
#pragma unroll
        for (int b = 0; b < 8; b++) {
            float v = hsum2(acc[r][b]);
            v += __shfl_xor_sync(0xffffffffu, v, 16);
            v += __shfl_xor_sync(0xffffffffu, v, 8);
            v += __shfl_xor_sync(0xffffffffu, v, 4);
            v += __shfl_xor_sync(0xffffffffu, v, 2);
            v += __shfl_xor_sync(0xffffffffu, v, 1);
            if (lane == b) res = v;
        }
        if (lane < 8)
            g_p[((size_t)cs * NROWS + r0 + r) * BSZ + b0 + lane] = res;
    }
}

// ---------------------------------------------------------------------------
// Kernel 2: combine col-split partials + RoPE (unchanged).
// ---------------------------------------------------------------------------
__global__ void k_fuse(const float* __restrict__ fc, const float* __restrict__ fs)
{
    const int t = blockIdx.x * blockDim.x + threadIdx.x;
    if (t < 32768) {                       // q pairs
        const int b = t >> 11, j = t & 2047;
        const int row = 2 * j;
        const float a  = g_p[(size_t)row * BSZ + b] + g_p[((size_t)NROWS + row) * BSZ + b];
        const float bb = g_p[(size_t)(row + 1) * BSZ + b] + g_p[((size_t)NROWS + row + 1) * BSZ + b];
        const float c = fc[j & 63], s = fs[j & 63];
        g_q[(size_t)b * DIM + row]     = a * c - bb * s;
        g_q[(size_t)b * DIM + row + 1] = a * s + bb * c;
    } else if (t < 40960) {                // k pairs
        const int u = t - 32768;
        const int b = u >> 9, j = u & 511;
        const int row = 4096 + 2 * j;
        const float a  = g_p[(size_t)row * BSZ + b] + g_p[((size_t)NROWS + row) * BSZ + b];
        const float bb = g_p[(size_t)(row + 1) * BSZ + b] + g_p[((size_t)NROWS + row + 1) * BSZ + b];
        const float c = fc[j & 63], s = fs[j & 63];
        g_k[(size_t)b * KVROW + 2 * j]     = a * c - bb * s;
        g_k[(size_t)b * KVROW + 2 * j + 1] = a * s + bb * c;
    } else if (t < 57344) {                // v elements
        const int u = t - 40960;
        const int b = u >> 10, e = u & 1023;
        const int row = 5120 + e;
        g_v[(size_t)b * KVROW + e] =
            g_p[(size_t)row * BSZ + b] + g_p[((size_t)NROWS + row) * BSZ + b];
    }
}

// ---------------------------------------------------------------------------
// Profiling shim: no-op launch to shift which kernel lands on the ncu
// capture index (previously k_combine; should now be k_attn).
// ---------------------------------------------------------------------------
__global__ void k_noop() {}

// ---------------------------------------------------------------------------
// Kernel 3: split-KV attention partials (exact R8/193.9 structure, chunk 128).
// ---------------------------------------------------------------------------
__global__ void __launch_bounds__(256) k_attn(
    const float* __restrict__ cache_k,
    const float* __restrict__ cache_v,
    const int*   __restrict__ sp_ptr)
{
    const int split = blockIdx.x;
    const int hk    = blockIdx.y;
    const int b     = blockIdx.z;
    const int sp    = load_sp(sp_ptr);
    const int pos0  = split * SCHUNK;
    const int tid   = threadIdx.x;
    const int lane  = tid & 31;
    const int warp  = tid >> 5;
    const bool pure = (pos0 + SCHUNK <= sp);

    __shared__ float  sc[4][SCHUNK];
    __shared__ float4 red4[8][4][32];
    __shared__ float  redm[4][8];
    __shared__ float  redl[4][8];
    __shared__ float  fm[4];

    float4 ql[4];
#pragma unroll
    for (int j = 0; j < 4; j++)
        ql[j] = *reinterpret_cast<const float4*>(
            g_q + (size_t)b * DIM + (hk * 4 + j) * HD + lane * 4);

    // ---- Phase A: scores + running per-head max ----
    const size_t kb = (size_t)b * MSL * KVROW + (size_t)hk * HD;
    float lmax = -1e30f;                       // head = lane & 3
    if (pure) {
        const float* kp = cache_k + kb + (size_t)pos0 * KVROW + lane * 4;
        for (int p = warp; p < SCHUNK; p += 32) {
            const float4 kA = *reinterpret_cast<const float4*>(kp + (size_t)(p     ) * KVROW);
            const float4 kB = *reinterpret_cast<const float4*>(kp + (size_t)(p +  8) * KVROW);
            const float4 kC = *reinterpret_cast<const float4*>(kp + (size_t)(p + 16) * KVROW);
            const float4 kD = *reinterpret_cast<const float4*>(kp + (size_t)(p + 24) * KVROW);
            const float cA = dot4r(kA, ql, lane) * SCALE;
            const float cB = dot4r(kB, ql, lane) * SCALE;
            const float cC = dot4r(kC, ql, lane) * SCALE;
            const float cD = dot4r(kD, ql, lane) * SCALE;
            if (lane < 4) {
                sc[lane][p]      = cA;
                sc[lane][p +  8] = cB;
                sc[lane][p + 16] = cC;
                sc[lane][p + 24] = cD;
            }
            lmax = fmaxf(lmax, fmaxf(fmaxf(cA, cB), fmaxf(cC, cD)));
        }
    } else {
        for (int p = warp; p < SCHUNK; p += 8) {
            const int pos = pos0 + p;
            float4 k4;
            if (pos < sp)
                k4 = *reinterpret_cast<const float4*>(
                    cache_k + kb + (size_t)pos * KVROW + lane * 4);
            else if (pos == sp)
                k4 = *reinterpret_cast<const float4*>(
                    g_k + (b * NKV + hk) * HD + lane * 4);
            else
                k4 = make_float4(0.f, 0.f, 0.f, 0.f);
            const float cc  = dot4r(k4, ql, lane) * SCALE;
            const float val = (pos <= sp) ? cc : -1e30f;
            if (lane < 4) sc[lane][p] = val;
            lmax = fmaxf(lmax, val);
        }
    }
    if (lane < 4) redm[lane][warp] = lmax;
    __syncthreads();
    if (tid < 4) {
        float m = redm[tid][0];
#pragma unroll
        for (int w = 1; w < 8; w++) m = fmaxf(m, redm[tid][w]);
        fm[tid] = m;
    }
    __syncthreads();

    // ---- exp + row-sum ----
    float ll[4] = {0.f, 0.f, 0.f, 0.f};
    for (int p = tid; p < SCHUNK; p += 256) {
#pragma unroll
        for (int h = 0; h < 4; h++) {
            const float e = __expf(sc[h][p] - fm[h]);
            sc[h][p] = e;
            ll[h] += e;
        }
    }
    {
        const float vv = dot4r(make_float4(0.f,0.f,0.f,0.f), ql, 0) * 0.f   // keep ql alive cheaply? no —
              + 0.f;
        (void)vv;
    }
#pragma unroll
    for (int h = 0; h < 4; h++) {
        float v = ll[h];
        v += __shfl_xor_sync(0xffffffffu, v, 16);
        v += __shfl_xor_sync(0xffffffffu, v, 8);
        v += __shfl_xor_sync(0xffffffffu, v, 4);
        v += __shfl_xor_sync(0xffffffffu, v, 2);
        v += __shfl_xor_sync(0xffffffffu, v, 1);
        if (lane == 0) redl[h][warp] = v;
    }
    __syncthreads();

    const size_t pi = (size_t)(b * NKV + hk) * NSPLIT + split;
    if (tid < 4) {
        float s = 0.f;
#pragma unroll
        for (int w = 0; w < 8; w++) s += redl[tid][w];
        g_m[pi * 4 + tid] = fm[tid];
        g_l[pi * 4 + tid] = s;
    }
    __syncthreads();

    // ---- Phase C: V stream ----
    float4 a0 = {0,0,0,0}, a1 = {0,0,0,0}, a2 = {0,0,0,0}, a3 = {0,0,0,0};
    const float* vb = cache_v + (size_t)b * MSL * KVROW + (size_t)hk * HD + lane * 4;
#define ACC4(PP, V4)                                                          \
    {   const float p0 = sc[0][PP], p1 = sc[1][PP],                           \
                    p2 = sc[2][PP], p3 = sc[3][PP];                           \
        a0.x = fmaf(p0, (V4).x, a0.x); a0.y = fmaf(p0, (V4).y, a0.y);         \
        a0.z = fmaf(p0, (V4).z, a0.z); a0.w = fmaf(p0, (V4).w, a0.w);         \
        a1.x = fmaf(p1, (V4).x, a1.x); a1.y = fmaf(p1, (V4).y, a1.y);         \
        a1.z = fmaf(p1, (V4).z, a1.z); a1.w = fmaf(p1, (V4).w, a1.w);         \
        a2.x = fmaf(p2, (V4).x, a2.x); a2.y = fmaf(p2, (V4).y, a2.y);         \
        a2.z = fmaf(p2, (V4).z, a2.z); a2.w = fmaf(p2, (V4).w, a2.w);         \
        a3.x = fmaf(p3, (V4).x, a3.x); a3.y = fmaf(p3, (V4).y, a3.y);         \
        a3.z = fmaf(p3, (V4).z, a3.z); a3.w = fmaf(p3, (V4).w, a3.w); }
    if (pure) {
        const float* vp = vb + (size_t)pos0 * KVROW;
        for (int p = warp; p < SCHUNK; p += 32) {
            const float4 vA = *reinterpret_cast<const float4*>(vp + (size_t)(p     ) * KVROW);
            const float4 vB = *reinterpret_cast<const float4*>(vp + (size_t)(p +  8) * KVROW);
            const float4 vC = *reinterpret_cast<const float4*>(vp + (size_t)(p + 16) * KVROW);
            const float4 vD = *reinterpret_cast<const float4*>(vp + (size_t)(p + 24) * KVROW);
            ACC4(p,      vA);
            ACC4(p +  8, vB);
            ACC4(p + 16, vC);
            ACC4(p + 24, vD);
        }
    } else {
        const float4 gv4 = *reinterpret_cast<const float4*>(
            g_v + (b * NKV + hk) * HD + lane * 4);
        for (int p = warp; p < SCHUNK; p += 8) {
            const int pos = pos0 + p;
            const float4 v4 = (pos == sp) ? gv4
                : *reinterpret_cast<const float4*>(vb + (size_t)pos * KVROW);
            ACC4(p, v4);
        }
    }
#undef ACC4
    red4[warp][0][lane] = a0;
    red4[warp][1][lane] = a1;
    red4[warp][2][lane] = a2;
    red4[warp][3][lane] = a3;
    __syncthreads();

    const float* redf = reinterpret_cast<const float*>(red4);
    float* op = g_op + pi * 4 * HD;
    for (int o = tid; o < 4 * HD; o += 256) {
        float s = 0.f;
#pragma unroll
        for (int w = 0; w < 8; w++) s += redf[w * 512 + o];
        op[o] = s;
    }
}

// ---------------------------------------------------------------------------
// Kernel 4: combine split partials into g_attn (NSPLIT=32 loop).
// ---------------------------------------------------------------------------
__global__ void k_combine()
{
    const int bh = blockIdx.x;
    const int d  = threadIdx.x;
    const int b  = bh >> 5, h = bh & 31;
    const int hk = h >> 2, j = h & 3;
    const int base = (b * NKV + hk) * NSPLIT;

    float M = -1e30f;
#pragma unroll
    for (int s = 0; s < NSPLIT; s++) M = fmaxf(M, g_m[(base + s) * 4 + j]);
    float den = 0.f, o = 0.f;
#pragma unroll
    for (int s = 0; s < NSPLIT; s++) {
        const float w = __expf(g_m[(base + s) * 4 + j] - M);
        den += g_l[(base + s) * 4 + j] * w;
        o   += g_op[((size_t)(base + s) * 4 + j) * HD + d] * w;
    }
    g_attn[b * DIM + h * HD + d] = o / den;
}

// ---------------------------------------------------------------------------
// Kernel 5: output GEMV (unchanged).
// ---------------------------------------------------------------------------
__global__ void __launch_bounds__(256, 3) k_gemv_out(
    const float* __restrict__ wo)
{
    const int warp = threadIdx.x >> 5;
    const int lane = threadIdx.x & 31;
    const int cs   = blockIdx.x & 1;
    const int bh   = (blockIdx.x >> 1) & 1;
    const int rb   = blockIdx.x >> 2;
    const int r0   = rb * 16 + warp * 2;
    const int b0   = bh * 8;
    const int c0   = cs * 2048;

    const float* w0p = wo + (size_t)(r0 + 0) * DIM + c0;
    const float* w1p = wo + (size_t)(r0 + 1) * DIM + c0;
    const float* xp  = g_attn + (size_t)b0 * DIM + c0;

    ull acc[2][8];
#pragma unroll
    for (int r = 0; r < 2; r++)
#pragma unroll
        for (int b = 0; b < 8; b++) acc[r][b] = 0ull;

    const int off = lane * 4;
    for (int c = 0; c < 2048; c += 256) {
        const ulonglong2 w0a = *reinterpret_cast<const ulonglong2*>(w0p + c + off);
        const ulonglong2 w1a = *reinterpret_cast<const ulonglong2*>(w1p + c + off);
        const ulonglong2 w0b = *reinterpret_cast<const ulonglong2*>(w0p + c + 128 + off);
        const ulonglong2 w1b = *reinterpret_cast<const ulonglong2*>(w1p + c + 128 + off);
#pragma unroll
        for (int b = 0; b < 8; b++) {
            const ulonglong2 xa =
                *reinterpret_cast<const ulonglong2*>(xp + (size_t)b * DIM + c + off);
            const ulonglong2 xb =
                *reinterpret_cast<const ulonglong2*>(xp + (size_t)b * DIM + c + 128 + off);
            acc[0][b] = ffma2(w0a.x, xa.x, acc[0][b]);
            acc[0][b] = ffma2(w0a.y, xa.y, acc[0][b]);
            acc[1][b] = ffma2(w1a.x, xa.x, acc[1][b]);
            acc[1][b] = ffma2(w1a.y, xa.y, acc[1][b]);
            acc[0][b] = ffma2(w0b.x, xb.x, acc[0][b]);
            acc[0][b] = ffma2(w0b.y, xb.y, acc[0][b]);
            acc[1][b] = ffma2(w1b.x, xb.x, acc[1][b]);
            acc[1][b] = ffma2(w1b.y, xb.y, acc[1][b]);
        }
    }

#pragma unroll
    for (int r = 0; r < 2; r++) {
        float res = 0.f;
#pragma unroll
        for (int b = 0; b < 8; b++) {
            float v = hsum2(acc[r][b]);
            v += __shfl_xor_sync(0xffffffffu, v, 16);
            v += __shfl_xor_sync(0xffffffffu, v, 8);
            v += __shfl_xor_sync(0xffffffffu, v, 4);
            v += __shfl_xor_sync(0xffffffffu, v, 2);
            v += __shfl_xor_sync(0xffffffffu, v, 1);
            if (lane == b) res = v;
        }
        if (lane < 8)
            g_po[((size_t)cs * DIM + r0 + r) * BSZ + b0 + lane] = res;
    }
}

// ---------------------------------------------------------------------------
// Kernel 6: combine output col-split partials -> d_out (unchanged).
// ---------------------------------------------------------------------------
__global__ void k_ocomb(float* __restrict__ out)
{
    const int t = blockIdx.x * blockDim.x + threadIdx.x;
    const int b = t >> 12, row = t & 4095;
    out[(size_t)b * DIM + row] =
        g_po[(size_t)row * BSZ + b] + g_po[((size_t)DIM + row) * BSZ + b];
}

// ---------------------------------------------------------------------------
extern "C" void kernel_launch(void* const* d_in, const int* in_sizes, int n_in,
                              void* d_out, int out_size)
{
    const float* x  = (const float*)d_in[0];
    const float* wq = (const float*)d_in[1];
    const float* wk = (const float*)d_in[2];
    const float* wv = (const float*)d_in[3];
    const float* wo = (const float*)d_in[4];
    const float* ck = (const float*)d_in[5];
    const float* cv = (const float*)d_in[6];
    const float* fc = (const float*)d_in[7];
    const float* fs = (const float*)d_in[8];
    const int*   sp = (const int*)d_in[9];
    float* out = (float*)d_out;

    k_gemv_qkv<<<1536, 256>>>(x, wq, wk, wv);
    k_fuse<<<224, 256>>>(fc, fs);
    k_noop<<<1, 32>>>();                    // shift ncu capture index onto k_attn
    dim3 ag(NSPLIT, NKV, BSZ);
    k_attn<<<ag, 256>>>(ck, cv, sp);
    k_combine<<<BSZ * NH, HD>>>();
    k_gemv_out<<<1024, 256>>>(wo);
    k_ocomb<<<256, 256>>>(out);
}